// round 3
// baseline (speedup 1.0000x reference)
#include <cuda_runtime.h>
#include <math.h>

#define EPS 1e-6f
#define TB 16
#define MAXN 4096
#define MAXPAIRS 2200000

__device__ float4 g_plane[MAXN];
__device__ unsigned int g_list[MAXPAIRS];
__device__ unsigned int g_count;

// Per-triangle plane (n, d): n.x + d = 0 through v0. Also resets worklist counter.
__global__ void prep_kernel(const float* __restrict__ T, int N) {
    int i = blockIdx.x * blockDim.x + threadIdx.x;
    if (i == 0) g_count = 0;
    if (i >= N) return;
    const float* t = T + (size_t)i * 9;
    float v0x = t[0], v0y = t[1], v0z = t[2];
    float e1x = t[3] - v0x, e1y = t[4] - v0y, e1z = t[5] - v0z;
    float e2x = t[6] - v0x, e2y = t[7] - v0y, e2z = t[8] - v0z;
    float nx = e1y * e2z - e1z * e2y;
    float ny = e1z * e2x - e1x * e2z;
    float nz = e1x * e2y - e1y * e2x;
    float d = -(nx * v0x + ny * v0y + nz * v0z);
    g_plane[i] = make_float4(nx, ny, nz, d);
}

__global__ void diag_kernel(float* __restrict__ out, int N) {
    int i = blockIdx.x * blockDim.x + threadIdx.x;
    if (i < N) out[(size_t)i * N + i] = 1.0f;
}

// Phase 1: plane-side reject over all upper-triangular pairs; push survivors.
__global__ void filter_kernel(const float* __restrict__ T, int N) {
    // Linear block index -> upper-triangular tile (ti <= tj).
    const int k = blockIdx.x;
    int tj = (int)((sqrtf(8.0f * (float)k + 1.0f) - 1.0f) * 0.5f);
    while ((tj + 1) * (tj + 2) / 2 <= k) tj++;
    while (tj * (tj + 1) / 2 > k) tj--;
    const int ti = k - tj * (tj + 1) / 2;

    __shared__ float trR[TB][9];
    __shared__ float trC[TB][9];
    __shared__ float4 nR[TB], nC[TB];

    const int tx = threadIdx.x, ty = threadIdx.y;
    const int tid = ty * TB + tx;
    const int i0 = ti * TB, j0 = tj * TB;

    for (int q = tid; q < TB * 9; q += TB * TB) {
        int r = q / 9, c = q % 9;
        int gi = i0 + r, gj = j0 + r;
        trR[r][c] = (gi < N) ? T[(size_t)gi * 9 + c] : 0.0f;
        trC[r][c] = (gj < N) ? T[(size_t)gj * 9 + c] : 0.0f;
    }
    if (tid < TB) {
        int gi = i0 + tid;
        nR[tid] = (gi < N) ? g_plane[gi] : make_float4(0, 0, 0, 0);
    } else if (tid < 2 * TB) {
        int gj = j0 + tid - TB;
        nC[tid - TB] = (gj < N) ? g_plane[gj] : make_float4(0, 0, 0, 0);
    }
    __syncthreads();

    const int i = i0 + ty;
    const int j = j0 + tx;

    bool cand = false;
    if (j > i && j < N) {
        const float* A = trR[ty];
        const float* B = trC[tx];
        const float4 na = nR[ty];
        const float4 nb = nC[tx];

        // Post-snap sign tests: snapped>0 <=> dd>=EPS ; snapped<0 <=> dd<=-EPS.
        bool pv = true, nv = true, pu = true, nu = true;
#pragma unroll
        for (int v = 0; v < 3; v++) {
            float dd = A[3 * v] * nb.x + A[3 * v + 1] * nb.y +
                       A[3 * v + 2] * nb.z + nb.w;
            pv &= (dd >= EPS);
            nv &= (dd <= -EPS);
            float ee = B[3 * v] * na.x + B[3 * v + 1] * na.y +
                       B[3 * v + 2] * na.z + na.w;
            pu &= (ee >= EPS);
            nu &= (ee <= -EPS);
        }
        cand = !(pv | nv) & !(pu | nu);
    }

    // Warp-aggregated push of survivors.
    unsigned mask = __ballot_sync(0xffffffffu, cand);
    if (mask) {
        int lane = tid & 31;
        int leader = __ffs(mask) - 1;
        unsigned base = 0;
        if (lane == leader) base = atomicAdd(&g_count, (unsigned)__popc(mask));
        base = __shfl_sync(0xffffffffu, base, leader);
        if (cand) {
            unsigned off = __popc(mask & ((1u << lane) - 1u));
            g_list[base + off] = ((unsigned)i << 16) | (unsigned)j;
        }
    }
}

__device__ __forceinline__ float sel3(int ax, float x, float y, float z) {
    return (ax == 0) ? x : ((ax == 1) ? y : z);
}

__device__ __forceinline__ void interval3(const float p[3], const float d[3],
                                          float& tmin, float& tmax) {
    tmin = INFINITY;
    tmax = -INFINITY;
#pragma unroll
    for (int k = 0; k < 3; k++) {
        const int kn = (k == 2) ? 0 : k + 1;
        float di = d[k], dj = d[kn];
        float pi = p[k], pj = p[kn];
        bool valid = (di * dj <= 0.0f) && !((di == 0.0f) && (dj == 0.0f));
        float denom = di - dj;
        float t = pi + (pj - pi) * __fdividef(di, (denom == 0.0f) ? 1.0f : denom);
        if (valid) {
            tmin = fminf(tmin, t);
            tmax = fmaxf(tmax, t);
        }
    }
}

// Phase 2: full interval test on compacted survivor list.
__global__ void solve_kernel(const float* __restrict__ T,
                             float* __restrict__ out, int N) {
    const unsigned count = g_count;
    for (unsigned idx = blockIdx.x * blockDim.x + threadIdx.x; idx < count;
         idx += gridDim.x * blockDim.x) {
        unsigned pk = g_list[idx];
        int i = (int)(pk >> 16);
        int j = (int)(pk & 0xffffu);

        float A[9], B[9];
        const float* ta = T + (size_t)i * 9;
        const float* tb = T + (size_t)j * 9;
#pragma unroll
        for (int c = 0; c < 9; c++) {
            A[c] = __ldg(ta + c);
            B[c] = __ldg(tb + c);
        }
        float4 na = g_plane[i];
        float4 nb = g_plane[j];

        float dv[3], du[3];
#pragma unroll
        for (int v = 0; v < 3; v++) {
            float dd = A[3 * v] * nb.x + A[3 * v + 1] * nb.y +
                       A[3 * v + 2] * nb.z + nb.w;
            dv[v] = (fabsf(dd) < EPS) ? 0.0f : dd;
            float ee = B[3 * v] * na.x + B[3 * v + 1] * na.y +
                       B[3 * v + 2] * na.z + na.w;
            du[v] = (fabsf(ee) < EPS) ? 0.0f : ee;
        }

        // Dominant axis of intersection-line direction (first-max argmax).
        float Dx = na.y * nb.z - na.z * nb.y;
        float Dy = na.z * nb.x - na.x * nb.z;
        float Dz = na.x * nb.y - na.y * nb.x;
        int ax = 0;
        float m = fabsf(Dx);
        if (fabsf(Dy) > m) { ax = 1; m = fabsf(Dy); }
        if (fabsf(Dz) > m) { ax = 2; }

        float pv[3] = {sel3(ax, A[0], A[1], A[2]),
                       sel3(ax, A[3], A[4], A[5]),
                       sel3(ax, A[6], A[7], A[8])};
        float pu[3] = {sel3(ax, B[0], B[1], B[2]),
                       sel3(ax, B[3], B[4], B[5]),
                       sel3(ax, B[6], B[7], B[8])};

        float t0v, t1v, t0u, t1u;
        interval3(pv, dv, t0v, t1v);
        interval3(pu, du, t0u, t1u);

        if (fmaxf(t0v, t0u) <= fminf(t1v, t1u)) {
            out[(size_t)i * N + j] = 1.0f;
            out[(size_t)j * N + i] = 1.0f;
        }
    }
}

extern "C" void kernel_launch(void* const* d_in, const int* in_sizes, int n_in,
                              void* d_out, int out_size) {
    const float* T = (const float*)d_in[0];
    float* out = (float*)d_out;
    int N = in_sizes[0] / 9;

    cudaMemsetAsync(d_out, 0, (size_t)out_size * sizeof(float), 0);
    prep_kernel<<<(N + 255) / 256, 256>>>(T, N);
    diag_kernel<<<(N + 255) / 256, 256>>>(out, N);

    int nt = (N + TB - 1) / TB;
    int nblk = nt * (nt + 1) / 2;
    filter_kernel<<<nblk, dim3(TB, TB)>>>(T, N);

    solve_kernel<<<4096, 256>>>(T, out, N);
}

// round 4
// speedup vs baseline: 2.3377x; 2.3377x over previous
#include <cuda_runtime.h>
#include <math.h>

#define EPS 1e-6f
#define TB 16

// Plane (n, d): n.x + d = 0 through v0; t = 9 floats in shared.
__device__ __forceinline__ float4 plane_of(const float* t) {
    float v0x = t[0], v0y = t[1], v0z = t[2];
    float e1x = t[3] - v0x, e1y = t[4] - v0y, e1z = t[5] - v0z;
    float e2x = t[6] - v0x, e2y = t[7] - v0y, e2z = t[8] - v0z;
    float nx = e1y * e2z - e1z * e2y;
    float ny = e1z * e2x - e1x * e2z;
    float nz = e1x * e2y - e1y * e2x;
    float d = -(nx * v0x + ny * v0y + nz * v0z);
    return make_float4(nx, ny, nz, d);
}

__device__ __forceinline__ void interval3(const float p[3], const float d[3],
                                          float& tmin, float& tmax) {
    tmin = INFINITY;
    tmax = -INFINITY;
#pragma unroll
    for (int k = 0; k < 3; k++) {
        const int kn = (k == 2) ? 0 : k + 1;
        float di = d[k], dj = d[kn];
        float pi = p[k], pj = p[kn];
        // valid => denom != 0 (proof: di==dj & di*dj<=0 => di=dj=0, excluded),
        // so divide unconditionally; invalid lanes' t is selected away below.
        bool valid = (di * dj <= 0.0f) & ((di != 0.0f) | (dj != 0.0f));
        float t = pi + (pj - pi) * __fdividef(di, di - dj);
        tmin = fminf(tmin, valid ? t : INFINITY);
        tmax = fmaxf(tmax, valid ? t : -INFINITY);
    }
}

__global__ __launch_bounds__(256) void pair_kernel(const float* __restrict__ T,
                                                   float* __restrict__ out,
                                                   int N) {
    // Linear block index -> upper-triangular tile (ti <= tj).
    const int k = blockIdx.x;
    int tj = (int)((sqrtf(8.0f * (float)k + 1.0f) - 1.0f) * 0.5f);
    while ((tj + 1) * (tj + 2) / 2 <= k) tj++;
    while (tj * (tj + 1) / 2 > k) tj--;
    const int ti = k - tj * (tj + 1) / 2;

    __shared__ float trR[TB][12];   // 48B rows: LDS.128 phase-conflict-free
    __shared__ float trC[TB][12];
    __shared__ float4 nR[TB], nC[TB];
    __shared__ float res[TB][TB + 1];

    const int tx = threadIdx.x, ty = threadIdx.y;
    const int tid = ty * TB + tx;
    const int i0 = ti * TB, j0 = tj * TB;

    for (int q = tid; q < TB * 9; q += TB * TB) {
        int r = q / 9, c = q % 9;
        int gi = i0 + r, gj = j0 + r;
        trR[r][c] = (gi < N) ? T[(size_t)gi * 9 + c] : 0.0f;
        trC[r][c] = (gj < N) ? T[(size_t)gj * 9 + c] : 0.0f;
    }
    __syncthreads();
    if (tid < TB) {
        nR[tid] = plane_of(trR[tid]);
    } else if (tid < 2 * TB) {
        nC[tid - TB] = plane_of(trC[tid - TB]);
    }
    __syncthreads();

    const int i = i0 + ty;
    const int j = j0 + tx;

    const float4 na = nR[ty];
    const float4 nb = nC[tx];

    // Signed distances (EPS-snapped), streamed from vectorized shared reads.
    float dv[3], du[3];
    {
        const float4* pa = (const float4*)trR[ty];
        float4 a0 = pa[0], a1 = pa[1], a2 = pa[2];
        float d0 = a0.x * nb.x + a0.y * nb.y + a0.z * nb.z + nb.w;
        float d1 = a0.w * nb.x + a1.x * nb.y + a1.y * nb.z + nb.w;
        float d2 = a1.z * nb.x + a1.w * nb.y + a2.x * nb.z + nb.w;
        dv[0] = (fabsf(d0) < EPS) ? 0.0f : d0;
        dv[1] = (fabsf(d1) < EPS) ? 0.0f : d1;
        dv[2] = (fabsf(d2) < EPS) ? 0.0f : d2;

        const float4* pb = (const float4*)trC[tx];
        float4 b0 = pb[0], b1 = pb[1], b2 = pb[2];
        float e0 = b0.x * na.x + b0.y * na.y + b0.z * na.z + na.w;
        float e1 = b0.w * na.x + b1.x * na.y + b1.y * na.z + na.w;
        float e2 = b1.z * na.x + b1.w * na.y + b2.x * na.z + na.w;
        du[0] = (fabsf(e0) < EPS) ? 0.0f : e0;
        du[1] = (fabsf(e1) < EPS) ? 0.0f : e1;
        du[2] = (fabsf(e2) < EPS) ? 0.0f : e2;
    }

    bool ssv = (dv[0] > 0.0f & dv[1] > 0.0f & dv[2] > 0.0f) |
               (dv[0] < 0.0f & dv[1] < 0.0f & dv[2] < 0.0f);
    bool ssu = (du[0] > 0.0f & du[1] > 0.0f & du[2] > 0.0f) |
               (du[0] < 0.0f & du[1] < 0.0f & du[2] < 0.0f);

    // Dominant axis of plane-plane line direction (first-max argmax).
    float Dx = na.y * nb.z - na.z * nb.y;
    float Dy = na.z * nb.x - na.x * nb.z;
    float Dz = na.x * nb.y - na.y * nb.x;
    int ax = 0;
    float m = fabsf(Dx);
    if (fabsf(Dy) > m) { ax = 1; m = fabsf(Dy); }
    if (fabsf(Dz) > m) { ax = 2; }

    // Fetch only the needed coordinate column (dynamic scalar LDS).
    float pv[3], pu[3];
#pragma unroll
    for (int v = 0; v < 3; v++) {
        pv[v] = trR[ty][3 * v + ax];
        pu[v] = trC[tx][3 * v + ax];
    }

    float t0v, t1v, t0u, t1u;
    interval3(pv, dv, t0v, t1v);
    interval3(pu, du, t0u, t1u);
    bool overlap = fmaxf(t0v, t0u) <= fminf(t1v, t1u);

    res[ty][tx] = (!ssv & !ssu & overlap) ? 1.0f : 0.0f;
    __syncthreads();

    // Upper (and diagonal) tile: coalesced row writes.
    if (i < N && j < N) {
        float val;
        if (ti == tj) {
            val = (tx > ty) ? res[ty][tx] : ((tx == ty) ? 1.0f : res[tx][ty]);
        } else {
            val = res[ty][tx];
        }
        out[(size_t)i * N + j] = val;
    }
    // Mirror tile for strictly-off-diagonal blocks (also coalesced).
    if (ti != tj) {
        int jj = j0 + ty, ii = i0 + tx;
        if (jj < N && ii < N) out[(size_t)jj * N + ii] = res[tx][ty];
    }
}

extern "C" void kernel_launch(void* const* d_in, const int* in_sizes, int n_in,
                              void* d_out, int out_size) {
    const float* T = (const float*)d_in[0];
    float* out = (float*)d_out;
    int N = in_sizes[0] / 9;

    int nt = (N + TB - 1) / TB;
    int nblk = nt * (nt + 1) / 2;
    pair_kernel<<<nblk, dim3(TB, TB)>>>(T, out, N);
}